// round 13
// baseline (speedup 1.0000x reference)
#include <cuda_runtime.h>
#include <cuda_bf16.h>
#include <cstdint>

#define BB 2
#define SS 2048
#define DD 1024
#define HH 16
#define KH 64
#define NBH 32
#define TSTR 144                 // smem row stride bytes (72 bf16)
#define A_SZ (128*TSTR)          // 18432
#define ASTG (2*A_SZ)            // 36864: A stage (hi+lo)
#define GEMM_SMEM (2*ASTG)       // 73728

__device__ __align__(16) __nv_bfloat16 g_xh[(size_t)BB*SS*DD], g_xl[(size_t)BB*SS*DD];
// B-fragment weights: per (p,h): [n16=4][k16=64][lane=32] uint4
__device__ uint4 g_wfh[3][HH][4*64*32], g_wfl[3][HH][4*64*32];
// B-fragment Wo: [n16=64][k16=64][lane=32]
__device__ uint4 g_wofh[64*64*32], g_wofl[64*64*32];
// A-fragment Q: [bh][qG=128][k16=4][lane]   (pre-scaled 1/8)
__device__ uint4 g_qfh[(size_t)NBH*128*4*32], g_qfl[(size_t)NBH*128*4*32];
// B-fragment K: [bh][kG=128][k16=4][lane]
__device__ uint4 g_kfh[(size_t)NBH*128*4*32], g_kfl[(size_t)NBH*128*4*32];
// V fp32 (QKV output), then B-fragment V^T: [bh][dn=4][k16=128][lane]
__device__ __align__(16) float g_vf[(size_t)NBH*SS*KH];
__device__ uint4 g_vfh[(size_t)NBH*4*128*32], g_vfl[(size_t)NBH*4*128*32];
// A-fragment ctx: [b][sG=128][k16=64][lane]
__device__ uint4 g_cfh[(size_t)BB*128*64*32], g_cfl[(size_t)BB*128*64*32];

// ---------------- helpers ----------------
__device__ __forceinline__ uint32_t cvta_smem(const void* p) {
    uint32_t a;
    asm("{ .reg .u64 t; cvta.to.shared.u64 t, %1; cvt.u32.u64 %0, t; }" : "=r"(a) : "l"(p));
    return a;
}
__device__ __forceinline__ void cpa16(uint32_t s, const void* g) {
    asm volatile("cp.async.cg.shared.global [%0], [%1], 16;" :: "r"(s), "l"(g) : "memory");
}
#define CPC()  asm volatile("cp.async.commit_group;" ::: "memory")
#define CPW0() asm volatile("cp.async.wait_group 0;" ::: "memory")
__device__ __forceinline__ void ldsm4(uint32_t r[4], uint32_t addr) {
    asm volatile("ldmatrix.sync.aligned.m8n8.x4.shared.b16 {%0,%1,%2,%3}, [%4];"
        : "=r"(r[0]), "=r"(r[1]), "=r"(r[2]), "=r"(r[3]) : "r"(addr));
}
__device__ __forceinline__ void mmabf(float c[4], const uint32_t a[4], uint32_t b0, uint32_t b1) {
    asm volatile("mma.sync.aligned.m16n8k16.row.col.f32.bf16.bf16.f32 "
        "{%0,%1,%2,%3}, {%4,%5,%6,%7}, {%8,%9}, {%0,%1,%2,%3};"
        : "+f"(c[0]), "+f"(c[1]), "+f"(c[2]), "+f"(c[3])
        : "r"(a[0]), "r"(a[1]), "r"(a[2]), "r"(a[3]), "r"(b0), "r"(b1));
}
__device__ __forceinline__ void mma_u4A(float c[4], uint4 a, uint32_t b0, uint32_t b1) {
    uint32_t ar[4] = {a.x, a.y, a.z, a.w};
    mmabf(c, ar, b0, b1);
}
__device__ __forceinline__ uint32_t pk2(float a, float b) {
    __nv_bfloat162 v = __floats2bfloat162_rn(a, b);
    return *(uint32_t*)&v;
}
__device__ __forceinline__ void split1(float v, __nv_bfloat16& h, float& lo) {
    h = __float2bfloat16(v);
    lo = v - __bfloat162float(h);
}
__device__ __forceinline__ float hi_of(float v) { return __bfloat162float(__float2bfloat16(v)); }
__device__ __forceinline__ float lo_of(float v) { return v - hi_of(v); }

// 3-term k16: A from smem (ldsm), B streamed fragment-major (k_qkv)
__device__ __forceinline__ void k16_fragB(float acc[][4], uint32_t Ah, uint32_t Al,
        const uint4* __restrict__ bfh, const uint4* __restrict__ bfl,
        int k16g, int nqb, int kk, int m0, int lane) {
    uint32_t ah[2][4], al[2][4];
#pragma unroll
    for (int mf = 0; mf < 2; mf++) {
        uint32_t ad = (uint32_t)((m0 + mf * 16 + (lane & 15)) * TSTR + (kk + ((lane >> 4) << 3)) * 2);
        ldsm4(ah[mf], Ah + ad);
        ldsm4(al[mf], Al + ad);
    }
#pragma unroll
    for (int nq = 0; nq < 2; nq++) {
        size_t bi = ((size_t)(nqb + nq) * 64 + k16g) * 32 + lane;
        uint4 bh4 = bfh[bi];
        uint4 bl4 = bfl[bi];
#pragma unroll
        for (int mf = 0; mf < 2; mf++) {
            float* c0 = acc[(mf * 2 + nq) * 2 + 0];
            float* c1 = acc[(mf * 2 + nq) * 2 + 1];
            mmabf(c0, ah[mf], bh4.x, bh4.y);
            mmabf(c1, ah[mf], bh4.z, bh4.w);
            mmabf(c0, ah[mf], bl4.x, bl4.y);
            mmabf(c1, ah[mf], bl4.z, bl4.w);
            mmabf(c0, al[mf], bh4.x, bh4.y);
            mmabf(c1, al[mf], bh4.z, bh4.w);
        }
    }
}

// ---------------- prep kernels ----------------
__global__ void k_xsplit(const float* __restrict__ x) {
    size_t i = (size_t)blockIdx.x * 256 + threadIdx.x;
    __nv_bfloat16 h; float lo; split1(x[i], h, lo);
    g_xh[i] = h; g_xl[i] = __float2bfloat16(lo);
}
__global__ void k_wsplit(const float* __restrict__ Wq, const float* __restrict__ Wk,
                         const float* __restrict__ Wv) {
    int gid = blockIdx.x * 256 + threadIdx.x;
    int lane = gid & 31;
    int k16  = (gid >> 5) & 63;
    int nq   = (gid >> 11) & 3;
    int h    = (gid >> 13) & 15;
    int p    = gid >> 17;
    const float* W = ((p == 0) ? Wq : (p == 1) ? Wk : Wv) + (size_t)h * DD * KH;
    int n0 = nq * 16 + (lane >> 2);
    int d0 = k16 * 16 + (lane & 3) * 2;
    float v[8];
#pragma unroll
    for (int e = 0; e < 8; e++) {
        int n = n0 + ((e >> 2) ? 8 : 0);
        int d = d0 + ((e >> 1) & 1) * 8 + (e & 1);
        v[e] = W[(size_t)d * KH + n];
    }
    float hv[8], lv[8];
#pragma unroll
    for (int e = 0; e < 8; e++) {
        __nv_bfloat16 hh; split1(v[e], hh, lv[e]);
        hv[e] = __bfloat162float(hh);
    }
    size_t idx = ((size_t)nq * 64 + k16) * 32 + lane;
    g_wfh[p][h][idx] = make_uint4(pk2(hv[0],hv[1]), pk2(hv[2],hv[3]), pk2(hv[4],hv[5]), pk2(hv[6],hv[7]));
    g_wfl[p][h][idx] = make_uint4(pk2(lv[0],lv[1]), pk2(lv[2],lv[3]), pk2(lv[4],lv[5]), pk2(lv[6],lv[7]));
}
__global__ void k_wosplit(const float* __restrict__ Wo) {
    int gid = blockIdx.x * 256 + threadIdx.x;
    int lane = gid & 31;
    int k16  = (gid >> 5) & 63;
    int n16  = gid >> 11;
    int n0 = n16 * 16 + (lane >> 2);
    int a0 = k16 * 16 + (lane & 3) * 2;
    float v[8];
#pragma unroll
    for (int e = 0; e < 8; e++) {
        int n = n0 + ((e >> 2) ? 8 : 0);
        int a = a0 + ((e >> 1) & 1) * 8 + (e & 1);
        v[e] = Wo[(size_t)a * DD + n];
    }
    float hv[8], lv[8];
#pragma unroll
    for (int e = 0; e < 8; e++) {
        __nv_bfloat16 hh; split1(v[e], hh, lv[e]);
        hv[e] = __bfloat162float(hh);
    }
    size_t idx = ((size_t)n16 * 64 + k16) * 32 + lane;
    g_wofh[idx] = make_uint4(pk2(hv[0],hv[1]), pk2(hv[2],hv[3]), pk2(hv[4],hv[5]), pk2(hv[6],hv[7]));
    g_wofl[idx] = make_uint4(pk2(lv[0],lv[1]), pk2(lv[2],lv[3]), pk2(lv[4],lv[5]), pk2(lv[6],lv[7]));
}
// V^T B-fragments from g_vf via smem transpose: block = (stile, bh)
__global__ __launch_bounds__(256) void k_vfrag() {
    __shared__ float sm[64][65];
    const int t = threadIdx.x, stile = blockIdx.x, bh = blockIdx.y;
    const float* src = g_vf + ((size_t)bh * SS + stile * 64) * KH;
#pragma unroll
    for (int i = 0; i < 16; i++) {
        int idx = t + i * 256, sr = idx >> 6, v = idx & 63;
        sm[sr][v] = src[(size_t)sr * KH + v];
    }
    __syncthreads();
#pragma unroll
    for (int rep = 0; rep < 2; rep++) {
        int pos = t + rep * 256;
        int lane = pos & 31, kt = (pos >> 5) & 3, dn = pos >> 7;
        int n0 = dn * 16 + (lane >> 2);
        int k0 = kt * 16 + (lane & 3) * 2;
        float hv[8], lv[8];
#pragma unroll
        for (int e = 0; e < 8; e++) {
            int n = n0 + ((e >> 2) ? 8 : 0);                  // dim
            int k = k0 + ((e >> 1) & 1) * 8 + (e & 1);        // key (local)
            float v = sm[k][n];
            __nv_bfloat16 hh; split1(v, hh, lv[e]);
            hv[e] = __bfloat162float(hh);
        }
        size_t idx = (((size_t)bh * 4 + dn) * 128 + stile * 4 + kt) * 32 + lane;
        g_vfh[idx] = make_uint4(pk2(hv[0],hv[1]), pk2(hv[2],hv[3]), pk2(hv[4],hv[5]), pk2(hv[6],hv[7]));
        g_vfl[idx] = make_uint4(pk2(lv[0],lv[1]), pk2(lv[2],lv[3]), pk2(lv[4],lv[5]), pk2(lv[6],lv[7]));
    }
}

// ---------------- tile loader ----------------
__device__ __forceinline__ void cp_tileA(uint32_t dst, const __nv_bfloat16* src, size_t ld, int t) {
#pragma unroll
    for (int i = 0; i < 4; i++) {
        int idx = t + i * 256, r = idx >> 3, u = idx & 7;
        cpa16(dst + (uint32_t)(r * TSTR + u * 16), src + (size_t)r * ld + u * 8);
    }
}

// ---------------- QKV projection: A smem, B streamed; Q/K emitted as fragments ----------------
__global__ __launch_bounds__(256) void k_qkv() {
    extern __shared__ char smraw[];
    const uint32_t sb = cvta_smem(smraw);
    const int t = threadIdx.x, lane = t & 31, w = t >> 5;
    const int m0 = (w & 3) * 32, nqb = (w >> 2) * 2;
    const int s0 = blockIdx.x * 128, bh = blockIdx.y, b = bh >> 4, h = bh & 15, p = blockIdx.z;

    const __nv_bfloat16* gAh = g_xh + ((size_t)b * SS + s0) * DD;
    const __nv_bfloat16* gAl = g_xl + ((size_t)b * SS + s0) * DD;
    const uint4* __restrict__ bfh = g_wfh[p][h];
    const uint4* __restrict__ bfl = g_wfl[p][h];

    cp_tileA(sb + 0,    gAh, DD, t);
    cp_tileA(sb + A_SZ, gAl, DD, t);
    CPC();

    float acc[8][4] = {};
    for (int c = 0; c < 16; c++) {
        CPW0();
        __syncthreads();
        if (c + 1 < 16) {
            uint32_t st = sb + (uint32_t)(((c + 1) & 1) * ASTG);
            cp_tileA(st + 0,    gAh + (c + 1) * 64, DD, t);
            cp_tileA(st + A_SZ, gAl + (c + 1) * 64, DD, t);
            CPC();
        }
        uint32_t cu = sb + (uint32_t)((c & 1) * ASTG);
#pragma unroll
        for (int kk = 0; kk < 64; kk += 16)
            k16_fragB(acc, cu, cu + A_SZ, bfh, bfl, c * 4 + (kk >> 4), nqb, kk, m0, lane);
    }

    const int l4 = lane >> 2, l2 = (lane & 3) << 1;
    if (p == 2) {
        float* dst = g_vf + ((size_t)bh * SS + s0) * KH;
#pragma unroll
        for (int mf = 0; mf < 2; mf++)
#pragma unroll
            for (int nq = 0; nq < 2; nq++)
#pragma unroll
                for (int hf = 0; hf < 2; hf++) {
                    float* c = acc[(mf * 2 + nq) * 2 + hf];
                    int R = m0 + mf * 16 + l4, C = nqb * 16 + nq * 16 + hf * 8 + l2;
                    *(float2*)(dst + (size_t)R * KH + C)       = make_float2(c[0], c[1]);
                    *(float2*)(dst + (size_t)(R + 8) * KH + C) = make_float2(c[2], c[3]);
                }
    } else if (p == 0) {
        // Q -> A-fragments, pre-scaled 1/8
#pragma unroll
        for (int mf = 0; mf < 2; mf++)
#pragma unroll
            for (int nq = 0; nq < 2; nq++) {
                float* c0 = acc[(mf * 2 + nq) * 2 + 0];  // hf=0: dims l2,l2+1
                float* c1 = acc[(mf * 2 + nq) * 2 + 1];  // hf=1: dims l2+8,l2+9
                float v[8] = {c0[0]*0.125f, c0[1]*0.125f, c0[2]*0.125f, c0[3]*0.125f,
                              c1[0]*0.125f, c1[1]*0.125f, c1[2]*0.125f, c1[3]*0.125f};
                int qG = (s0 + m0 + mf * 16) >> 4;
                int k16d = nqb + nq;
                size_t idx = (((size_t)bh * 128 + qG) * 4 + k16d) * 32 + lane;
                // A-frag: x=(r,c0),(r,c0+1)  y=(r+8,c0),(r+8,c0+1)  z=(r,c0+8).. w=(r+8,c0+8)..
                g_qfh[idx] = make_uint4(pk2(hi_of(v[0]), hi_of(v[1])), pk2(hi_of(v[2]), hi_of(v[3])),
                                        pk2(hi_of(v[4]), hi_of(v[5])), pk2(hi_of(v[6]), hi_of(v[7])));
                g_qfl[idx] = make_uint4(pk2(lo_of(v[0]), lo_of(v[1])), pk2(lo_of(v[2]), lo_of(v[3])),
                                        pk2(lo_of(v[4]), lo_of(v[5])), pk2(lo_of(v[6]), lo_of(v[7])));
            }
    } else {
        // K -> B-fragments
#pragma unroll
        for (int mf = 0; mf < 2; mf++)
#pragma unroll
            for (int nq = 0; nq < 2; nq++) {
                float* c0 = acc[(mf * 2 + nq) * 2 + 0];
                float* c1 = acc[(mf * 2 + nq) * 2 + 1];
                int kG = (s0 + m0 + mf * 16) >> 4;
                int k16d = nqb + nq;
                size_t idx = (((size_t)bh * 128 + kG) * 4 + k16d) * 32 + lane;
                // B-frag: x=(n,k0),(n,k0+1)  y=(n,k0+8),(n,k0+9)  z=(n+8,k0).. w=(n+8,k0+8)..
                g_kfh[idx] = make_uint4(pk2(hi_of(c0[0]), hi_of(c0[1])), pk2(hi_of(c1[0]), hi_of(c1[1])),
                                        pk2(hi_of(c0[2]), hi_of(c0[3])), pk2(hi_of(c1[2]), hi_of(c1[3])));
                g_kfl[idx] = make_uint4(pk2(lo_of(c0[0]), lo_of(c0[1])), pk2(lo_of(c1[0]), lo_of(c1[1])),
                                        pk2(lo_of(c0[2]), lo_of(c0[3])), pk2(lo_of(c1[2]), lo_of(c1[3])));
            }
    }
}

// ---------------- flash attention: all operands fragment-streamed; no smem, no syncs ----------------
__global__ __launch_bounds__(256) void k_attn() {
    const int t = threadIdx.x, lane = t & 31, w = t >> 5;
    const int bh = blockIdx.y, q0 = blockIdx.x * 128;
    const int qG = (q0 >> 4) + w;             // this warp's 16 query rows
    const int l4 = lane >> 2, l2 = (lane & 3) << 1;

    const uint4* __restrict__ qfh = g_qfh + ((size_t)bh * 128 + qG) * 4 * 32;
    const uint4* __restrict__ qfl = g_qfl + ((size_t)bh * 128 + qG) * 4 * 32;
    const uint4* __restrict__ kfh = g_kfh + (size_t)bh * 128 * 4 * 32;
    const uint4* __restrict__ kfl = g_kfl + (size_t)bh * 128 * 4 * 32;
    const uint4* __restrict__ vfh = g_vfh + (size_t)bh * 4 * 128 * 32;
    const uint4* __restrict__ vfl = g_vfl + (size_t)bh * 4 * 128 * 32;

    float accO[8][4] = {};
    float lr0 = 0.f, lr1 = 0.f;

    for (int j = 0; j < 32; j++) {
        float s[8][4] = {};
#pragma unroll
        for (int kk = 0; kk < 4; kk++) {
            uint4 ah = qfh[kk * 32 + lane];
            uint4 al = qfl[kk * 32 + lane];
#pragma unroll
            for (int nq = 0; nq < 4; nq++) {
                size_t bi = ((size_t)(j * 4 + nq) * 4 + kk) * 32 + lane;
                uint4 bh4 = kfh[bi];
                uint4 bl4 = kfl[bi];
                float* c0 = s[nq * 2 + 0];
                float* c1 = s[nq * 2 + 1];
                mma_u4A(c0, ah, bh4.x, bh4.y);
                mma_u4A(c1, ah, bh4.z, bh4.w);
                mma_u4A(c0, ah, bl4.x, bl4.y);
                mma_u4A(c1, ah, bl4.z, bl4.w);
                mma_u4A(c0, al, bh4.x, bh4.y);
                mma_u4A(c1, al, bh4.z, bh4.w);
            }
        }

        // exp + split + pack P as A-fragments in registers
        float p1 = 0.f, p2 = 0.f;
        uint32_t pah[4][4], pal[4][4];
#pragma unroll
        for (int kt = 0; kt < 4; kt++) {
            float eh[8], el[8];
#pragma unroll
            for (int hf = 0; hf < 2; hf++) {
                float* c = s[kt * 2 + hf];
                float e0 = __expf(c[0]), e1 = __expf(c[1]);
                float e2 = __expf(c[2]), e3 = __expf(c[3]);
                p1 += e0 + e1; p2 += e2 + e3;
                __nv_bfloat16 hb; float lo;
                split1(e0, hb, lo); eh[hf * 4 + 0] = __bfloat162float(hb); el[hf * 4 + 0] = lo;
                split1(e1, hb, lo); eh[hf * 4 + 1] = __bfloat162float(hb); el[hf * 4 + 1] = lo;
                split1(e2, hb, lo); eh[hf * 4 + 2] = __bfloat162float(hb); el[hf * 4 + 2] = lo;
                split1(e3, hb, lo); eh[hf * 4 + 3] = __bfloat162float(hb); el[hf * 4 + 3] = lo;
            }
            pah[kt][0] = pk2(eh[0], eh[1]); pah[kt][1] = pk2(eh[2], eh[3]);
            pah[kt][2] = pk2(eh[4], eh[5]); pah[kt][3] = pk2(eh[6], eh[7]);
            pal[kt][0] = pk2(el[0], el[1]); pal[kt][1] = pk2(el[2], el[3]);
            pal[kt][2] = pk2(el[4], el[5]); pal[kt][3] = pk2(el[6], el[7]);
        }
        p1 += __shfl_xor_sync(0xFFFFFFFFu, p1, 1);
        p1 += __shfl_xor_sync(0xFFFFFFFFu, p1, 2);
        p2 += __shfl_xor_sync(0xFFFFFFFFu, p2, 1);
        p2 += __shfl_xor_sync(0xFFFFFFFFu, p2, 2);
        lr0 += p1; lr1 += p2;

        // PV: P (register A-frags) x V^T (streamed B-frags)
#pragma unroll
        for (int kt = 0; kt < 4; kt++) {
#pragma unroll
            for (int dn = 0; dn < 4; dn++) {
                size_t bi = ((size_t)dn * 128 + j * 4 + kt) * 32 + lane;
                uint4 bh4 = vfh[bi];
                uint4 bl4 = vfl[bi];
                float* c0 = accO[dn * 2 + 0];
                float* c1 = accO[dn * 2 + 1];
                mmabf(c0, pah[kt], bh4.x, bh4.y);
                mmabf(c1, pah[kt], bh4.z, bh4.w);
                mmabf(c0, pah[kt], bl4.x, bl4.y);
                mmabf(c1, pah[kt], bl4.z, bl4.w);
                mmabf(c0, pal[kt], bh4.x, bh4.y);
                mmabf(c1, pal[kt], bh4.z, bh4.w);
            }
        }
    }

    // ctx -> A-fragments for k_out
    const float i0 = 1.f / lr0, i1 = 1.f / lr1;
    const int b = bh >> 4, h = bh & 15;
#pragma unroll
    for (int dn = 0; dn < 4; dn++) {
        float* c0 = accO[dn * 2 + 0];
        float* c1 = accO[dn * 2 + 1];
        float v[8] = {c0[0]*i0, c0[1]*i0, c0[2]*i1, c0[3]*i1,
                      c1[0]*i0, c1[1]*i0, c1[2]*i1, c1[3]*i1};
        size_t idx = (((size_t)b * 128 + qG) * 64 + h * 4 + dn) * 32 + lane;
        g_cfh[idx] = make_uint4(pk2(hi_of(v[0]), hi_of(v[1])), pk2(hi_of(v[2]), hi_of(v[3])),
                                pk2(hi_of(v[4]), hi_of(v[5])), pk2(hi_of(v[6]), hi_of(v[7])));
        g_cfl[idx] = make_uint4(pk2(lo_of(v[0]), lo_of(v[1])), pk2(lo_of(v[2]), lo_of(v[3])),
                                pk2(lo_of(v[4]), lo_of(v[5])), pk2(lo_of(v[6]), lo_of(v[7])));
    }
}

// ---------------- output projection: fully fragment-streamed; no smem, no syncs ----------------
__global__ __launch_bounds__(256) void k_out(float* __restrict__ out) {
    const int t = threadIdx.x, lane = t & 31, w = t >> 5;
    const int m0 = (w & 3) * 32;
    const int b = blockIdx.x >> 4, s0 = (blockIdx.x & 15) * 128, n0g = blockIdx.y * 64;
    const int nqb = (n0g >> 4) + (w >> 2) * 2;

    float acc[8][4] = {};
    for (int kg = 0; kg < 64; kg++) {
        uint4 ah[2], al[2];
#pragma unroll
        for (int mf = 0; mf < 2; mf++) {
            size_t ai = (((size_t)b * 128 + ((s0 + m0 + mf * 16) >> 4)) * 64 + kg) * 32 + lane;
            ah[mf] = g_cfh[ai];
            al[mf] = g_cfl[ai];
        }
#pragma unroll
        for (int nq = 0; nq < 2; nq++) {
            size_t bi = ((size_t)(nqb + nq) * 64 + kg) * 32 + lane;
            uint4 bh4 = g_wofh[bi];
            uint4 bl4 = g_wofl[bi];
#pragma unroll
            for (int mf = 0; mf < 2; mf++) {
                float* c0 = acc[(mf * 2 + nq) * 2 + 0];
                float* c1 = acc[(mf * 2 + nq) * 2 + 1];
                mma_u4A(c0, ah[mf], bh4.x, bh4.y);
                mma_u4A(c1, ah[mf], bh4.z, bh4.w);
                mma_u4A(c0, ah[mf], bl4.x, bl4.y);
                mma_u4A(c1, ah[mf], bl4.z, bl4.w);
                mma_u4A(c0, al[mf], bh4.x, bh4.y);
                mma_u4A(c1, al[mf], bh4.z, bh4.w);
            }
        }
    }

    const int l4 = lane >> 2, l2 = (lane & 3) << 1;
    const int n0 = (w >> 2) * 32;
    float* dst = out + (size_t)(b * SS + s0) * DD + n0g;
#pragma unroll
    for (int mf = 0; mf < 2; mf++)
#pragma unroll
        for (int nq = 0; nq < 2; nq++)
#pragma unroll
            for (int hf = 0; hf < 2; hf++) {
                float* c = acc[(mf * 2 + nq) * 2 + hf];
                int R = m0 + mf * 16 + l4, C = n0 + nq * 16 + hf * 8 + l2;
                *(float2*)(dst + (size_t)R * DD + C)       = make_float2(c[0], c[1]);
                *(float2*)(dst + (size_t)(R + 8) * DD + C) = make_float2(c[2], c[3]);
            }
}

// ---------------------------------------------------------------------------
extern "C" void kernel_launch(void* const* d_in, const int* in_sizes, int n_in,
                              void* d_out, int out_size) {
    const float* x  = (const float*)d_in[0];
    const float* Wq = (const float*)d_in[1];
    const float* Wk = (const float*)d_in[2];
    const float* Wv = (const float*)d_in[3];
    const float* Wo = (const float*)d_in[4];
    float* out = (float*)d_out;

    cudaFuncSetAttribute(k_qkv, cudaFuncAttributeMaxDynamicSharedMemorySize, GEMM_SMEM);

    k_xsplit<<<(BB * SS * DD) / 256, 256>>>(x);
    k_wsplit<<<1536, 256>>>(Wq, Wk, Wv);
    k_wosplit<<<512, 256>>>(Wo);
    k_qkv<<<dim3(16, NBH, 3), 256, GEMM_SMEM>>>();
    k_vfrag<<<dim3(32, NBH), 256>>>();
    k_attn<<<dim3(16, NBH), 256>>>();
    k_out<<<dim3(32, 16), 256>>>(out);
}

// round 14
// speedup vs baseline: 1.4449x; 1.4449x over previous
#include <cuda_runtime.h>
#include <cuda_bf16.h>
#include <cstdint>

#define BB 2
#define SS 2048
#define DD 1024
#define HH 16
#define KH 64
#define NBH 32
#define QE ((size_t)NBH*SS*KH)
#define TSTR 144                 // smem row stride bytes (72 bf16)
#define A_SZ (128*TSTR)          // 18432
#define B_SZ (64*TSTR)           // 9216
#define ASTG (2*A_SZ)            // 36864: A-only stage (hi+lo)
#define GEMM_SMEM (2*ASTG)       // 73728
#define KVSTG (4*B_SZ)           // 36864 per KV stage (Kh,Kl,Vh,Vl)
#define ATTN_SMEM (2*A_SZ + 2*KVSTG)  // 110592 -> 2 CTAs/SM

__device__ __align__(16) __nv_bfloat16 g_xh[(size_t)BB*SS*DD], g_xl[(size_t)BB*SS*DD];
// B-fragment weights: per (p,h): [n16=4][k16=64][lane=32] uint4
__device__ uint4 g_wfh[3][HH][4*64*32], g_wfl[3][HH][4*64*32];
// B-fragment Wo: [n16=64][k16=64][lane=32]
__device__ uint4 g_wofh[64*64*32], g_wofl[64*64*32];
__device__ __align__(16) __nv_bfloat16 g_qh[QE], g_ql[QE], g_kh2[QE], g_kl2[QE];
__device__ __align__(16) float        g_vf[QE];
__device__ __align__(16) __nv_bfloat16 g_vth[QE], g_vtl[QE];
// A-fragment ctx: [b][sG=128][k16=64][lane]
__device__ uint4 g_cfh[(size_t)BB*128*64*32], g_cfl[(size_t)BB*128*64*32];

// ---------------- helpers ----------------
__device__ __forceinline__ uint32_t cvta_smem(const void* p) {
    uint32_t a;
    asm("{ .reg .u64 t; cvta.to.shared.u64 t, %1; cvt.u32.u64 %0, t; }" : "=r"(a) : "l"(p));
    return a;
}
__device__ __forceinline__ void cpa16(uint32_t s, const void* g) {
    asm volatile("cp.async.cg.shared.global [%0], [%1], 16;" :: "r"(s), "l"(g) : "memory");
}
#define CPC()  asm volatile("cp.async.commit_group;" ::: "memory")
#define CPW0() asm volatile("cp.async.wait_group 0;" ::: "memory")
__device__ __forceinline__ void ldsm4(uint32_t r[4], uint32_t addr) {
    asm volatile("ldmatrix.sync.aligned.m8n8.x4.shared.b16 {%0,%1,%2,%3}, [%4];"
        : "=r"(r[0]), "=r"(r[1]), "=r"(r[2]), "=r"(r[3]) : "r"(addr));
}
__device__ __forceinline__ void mmabf(float c[4], const uint32_t a[4], uint32_t b0, uint32_t b1) {
    asm volatile("mma.sync.aligned.m16n8k16.row.col.f32.bf16.bf16.f32 "
        "{%0,%1,%2,%3}, {%4,%5,%6,%7}, {%8,%9}, {%0,%1,%2,%3};"
        : "+f"(c[0]), "+f"(c[1]), "+f"(c[2]), "+f"(c[3])
        : "r"(a[0]), "r"(a[1]), "r"(a[2]), "r"(a[3]), "r"(b0), "r"(b1));
}
__device__ __forceinline__ void mma_u4A(float c[4], uint4 a, uint32_t b0, uint32_t b1) {
    uint32_t ar[4] = {a.x, a.y, a.z, a.w};
    mmabf(c, ar, b0, b1);
}
__device__ __forceinline__ uint32_t pk2(float a, float b) {
    __nv_bfloat162 v = __floats2bfloat162_rn(a, b);
    return *(uint32_t*)&v;
}
__device__ __forceinline__ void split1(float v, __nv_bfloat16& h, float& lo) {
    h = __float2bfloat16(v);
    lo = v - __bfloat162float(h);
}
__device__ __forceinline__ float hi_of(float v) { return __bfloat162float(__float2bfloat16(v)); }
__device__ __forceinline__ float lo_of(float v) { return v - hi_of(v); }

// 3-term compensated k16, both operands smem (attn QK path)
template<int MF, int NQ>
__device__ __forceinline__ void k16_all(float acc[][4], uint32_t Ah, uint32_t Al,
                                        uint32_t Bh, uint32_t Bl, int kk, int m0, int n0, int lane) {
    uint32_t ah[MF][4], al[MF][4], bh[NQ][4], bl[NQ][4];
#pragma unroll
    for (int mf = 0; mf < MF; mf++) {
        uint32_t ad = (uint32_t)((m0 + mf * 16 + (lane & 15)) * TSTR + (kk + ((lane >> 4) << 3)) * 2);
        ldsm4(ah[mf], Ah + ad);
        ldsm4(al[mf], Al + ad);
    }
#pragma unroll
    for (int nq = 0; nq < NQ; nq++) {
        uint32_t bd = (uint32_t)((n0 + nq * 16 + ((lane >> 4) << 3) + (lane & 7)) * TSTR
                                 + (kk + (((lane >> 3) & 1) << 3)) * 2);
        ldsm4(bh[nq], Bh + bd);
        ldsm4(bl[nq], Bl + bd);
    }
#pragma unroll
    for (int mf = 0; mf < MF; mf++)
#pragma unroll
        for (int nq = 0; nq < NQ; nq++) {
            float* c0 = acc[(mf * NQ + nq) * 2 + 0];
            float* c1 = acc[(mf * NQ + nq) * 2 + 1];
            mmabf(c0, ah[mf], bh[nq][0], bh[nq][1]);
            mmabf(c1, ah[mf], bh[nq][2], bh[nq][3]);
            mmabf(c0, ah[mf], bl[nq][0], bl[nq][1]);
            mmabf(c1, ah[mf], bl[nq][2], bl[nq][3]);
            mmabf(c0, al[mf], bh[nq][0], bh[nq][1]);
            mmabf(c1, al[mf], bh[nq][2], bh[nq][3]);
        }
}
// 3-term k16 with A from smem (ldsm) and B streamed fragment-major (k_qkv)
__device__ __forceinline__ void k16_fragB(float acc[][4], uint32_t Ah, uint32_t Al,
        const uint4* __restrict__ bfh, const uint4* __restrict__ bfl,
        int k16g, int nqb, int kk, int m0, int lane) {
    uint32_t ah[2][4], al[2][4];
#pragma unroll
    for (int mf = 0; mf < 2; mf++) {
        uint32_t ad = (uint32_t)((m0 + mf * 16 + (lane & 15)) * TSTR + (kk + ((lane >> 4) << 3)) * 2);
        ldsm4(ah[mf], Ah + ad);
        ldsm4(al[mf], Al + ad);
    }
#pragma unroll
    for (int nq = 0; nq < 2; nq++) {
        size_t bi = ((size_t)(nqb + nq) * 64 + k16g) * 32 + lane;
        uint4 bh4 = bfh[bi];
        uint4 bl4 = bfl[bi];
#pragma unroll
        for (int mf = 0; mf < 2; mf++) {
            float* c0 = acc[(mf * 2 + nq) * 2 + 0];
            float* c1 = acc[(mf * 2 + nq) * 2 + 1];
            mmabf(c0, ah[mf], bh4.x, bh4.y);
            mmabf(c1, ah[mf], bh4.z, bh4.w);
            mmabf(c0, ah[mf], bl4.x, bl4.y);
            mmabf(c1, ah[mf], bl4.z, bl4.w);
            mmabf(c0, al[mf], bh4.x, bh4.y);
            mmabf(c1, al[mf], bh4.z, bh4.w);
        }
    }
}
// PV with register-resident P fragments (hi/lo), 3-term vs split V (attn)
__device__ __forceinline__ void k16_pv_reg(float acc[][4], const uint32_t ph[4], const uint32_t pl[4],
                                           uint32_t Vh, uint32_t Vl, int kk, int lane) {
    uint32_t bh[4][4], bl[4][4];
#pragma unroll
    for (int nq = 0; nq < 4; nq++) {
        uint32_t bd = (uint32_t)((nq * 16 + ((lane >> 4) << 3) + (lane & 7)) * TSTR
                                 + (kk + (((lane >> 3) & 1) << 3)) * 2);
        ldsm4(bh[nq], Vh + bd);
        ldsm4(bl[nq], Vl + bd);
    }
#pragma unroll
    for (int nq = 0; nq < 4; nq++) {
        float* c0 = acc[nq * 2 + 0];
        float* c1 = acc[nq * 2 + 1];
        mmabf(c0, ph, bh[nq][0], bh[nq][1]);
        mmabf(c1, ph, bh[nq][2], bh[nq][3]);
        mmabf(c0, ph, bl[nq][0], bl[nq][1]);
        mmabf(c1, ph, bl[nq][2], bl[nq][3]);
        mmabf(c0, pl, bh[nq][0], bh[nq][1]);
        mmabf(c1, pl, bh[nq][2], bh[nq][3]);
    }
}

// ---------------- prep kernels ----------------
__global__ void k_xsplit(const float* __restrict__ x) {
    size_t i = (size_t)blockIdx.x * 256 + threadIdx.x;
    __nv_bfloat16 h; float lo; split1(x[i], h, lo);
    g_xh[i] = h; g_xl[i] = __float2bfloat16(lo);
}
__global__ void k_wsplit(const float* __restrict__ Wq, const float* __restrict__ Wk,
                         const float* __restrict__ Wv) {
    int gid = blockIdx.x * 256 + threadIdx.x;
    int lane = gid & 31;
    int k16  = (gid >> 5) & 63;
    int nq   = (gid >> 11) & 3;
    int h    = (gid >> 13) & 15;
    int p    = gid >> 17;
    const float* W = ((p == 0) ? Wq : (p == 1) ? Wk : Wv) + (size_t)h * DD * KH;
    int n0 = nq * 16 + (lane >> 2);
    int d0 = k16 * 16 + (lane & 3) * 2;
    float v[8];
#pragma unroll
    for (int e = 0; e < 8; e++) {
        int n = n0 + ((e >> 2) ? 8 : 0);
        int d = d0 + ((e >> 1) & 1) * 8 + (e & 1);
        v[e] = W[(size_t)d * KH + n];
    }
    float hv[8], lv[8];
#pragma unroll
    for (int e = 0; e < 8; e++) {
        __nv_bfloat16 hh; split1(v[e], hh, lv[e]);
        hv[e] = __bfloat162float(hh);
    }
    size_t idx = ((size_t)nq * 64 + k16) * 32 + lane;
    g_wfh[p][h][idx] = make_uint4(pk2(hv[0],hv[1]), pk2(hv[2],hv[3]), pk2(hv[4],hv[5]), pk2(hv[6],hv[7]));
    g_wfl[p][h][idx] = make_uint4(pk2(lv[0],lv[1]), pk2(lv[2],lv[3]), pk2(lv[4],lv[5]), pk2(lv[6],lv[7]));
}
__global__ void k_wosplit(const float* __restrict__ Wo) {
    int gid = blockIdx.x * 256 + threadIdx.x;
    int lane = gid & 31;
    int k16  = (gid >> 5) & 63;
    int n16  = gid >> 11;
    int n0 = n16 * 16 + (lane >> 2);
    int a0 = k16 * 16 + (lane & 3) * 2;
    float v[8];
#pragma unroll
    for (int e = 0; e < 8; e++) {
        int n = n0 + ((e >> 2) ? 8 : 0);
        int a = a0 + ((e >> 1) & 1) * 8 + (e & 1);
        v[e] = Wo[(size_t)a * DD + n];
    }
    float hv[8], lv[8];
#pragma unroll
    for (int e = 0; e < 8; e++) {
        __nv_bfloat16 hh; split1(v[e], hh, lv[e]);
        hv[e] = __bfloat162float(hh);
    }
    size_t idx = ((size_t)n16 * 64 + k16) * 32 + lane;
    g_wofh[idx] = make_uint4(pk2(hv[0],hv[1]), pk2(hv[2],hv[3]), pk2(hv[4],hv[5]), pk2(hv[6],hv[7]));
    g_wofl[idx] = make_uint4(pk2(lv[0],lv[1]), pk2(lv[2],lv[3]), pk2(lv[4],lv[5]), pk2(lv[6],lv[7]));
}
__global__ void k_vsplit() {
    __shared__ float tl[32][33];
    int s0 = blockIdx.x * 32, v0 = blockIdx.y * 32, bh = blockIdx.z;
    int tx = threadIdx.x, ty = threadIdx.y;
    const float* src = g_vf + (size_t)bh * SS * KH;
#pragma unroll
    for (int i = 0; i < 4; i++) tl[ty + i * 8][tx] = src[(size_t)(s0 + ty + i * 8) * KH + v0 + tx];
    __syncthreads();
#pragma unroll
    for (int i = 0; i < 4; i++) {
        int v = v0 + ty + i * 8, s = s0 + tx;
        __nv_bfloat16 hh; float lo; split1(tl[tx][ty + i * 8], hh, lo);
        g_vth[((size_t)bh * KH + v) * SS + s] = hh;
        g_vtl[((size_t)bh * KH + v) * SS + s] = __float2bfloat16(lo);
    }
}

// ---------------- tile loaders ----------------
__device__ __forceinline__ void cp_tileA(uint32_t dst, const __nv_bfloat16* src, size_t ld, int t) {
#pragma unroll
    for (int i = 0; i < 4; i++) {
        int idx = t + i * 256, r = idx >> 3, u = idx & 7;
        cpa16(dst + (uint32_t)(r * TSTR + u * 16), src + (size_t)r * ld + u * 8);
    }
}
__device__ __forceinline__ void cp_tileB(uint32_t dst, const __nv_bfloat16* src, size_t ld, int t) {
#pragma unroll
    for (int i = 0; i < 2; i++) {
        int idx = t + i * 256, r = idx >> 3, u = idx & 7;
        cpa16(dst + (uint32_t)(r * TSTR + u * 16), src + (size_t)r * ld + u * 8);
    }
}

// ---------------- QKV projection (R12: A smem double-buffered, B streamed) ----------------
__global__ __launch_bounds__(256) void k_qkv() {
    extern __shared__ char smraw[];
    const uint32_t sb = cvta_smem(smraw);
    const int t = threadIdx.x, lane = t & 31, w = t >> 5;
    const int m0 = (w & 3) * 32, nqb = (w >> 2) * 2;
    const int s0 = blockIdx.x * 128, bh = blockIdx.y, b = bh >> 4, h = bh & 15, p = blockIdx.z;

    const __nv_bfloat16* gAh = g_xh + ((size_t)b * SS + s0) * DD;
    const __nv_bfloat16* gAl = g_xl + ((size_t)b * SS + s0) * DD;
    const uint4* __restrict__ bfh = g_wfh[p][h];
    const uint4* __restrict__ bfl = g_wfl[p][h];

    cp_tileA(sb + 0,    gAh, DD, t);
    cp_tileA(sb + A_SZ, gAl, DD, t);
    CPC();

    float acc[8][4] = {};
    for (int c = 0; c < 16; c++) {
        CPW0();
        __syncthreads();
        if (c + 1 < 16) {
            uint32_t st = sb + (uint32_t)(((c + 1) & 1) * ASTG);
            cp_tileA(st + 0,    gAh + (c + 1) * 64, DD, t);
            cp_tileA(st + A_SZ, gAl + (c + 1) * 64, DD, t);
            CPC();
        }
        uint32_t cu = sb + (uint32_t)((c & 1) * ASTG);
#pragma unroll
        for (int kk = 0; kk < 64; kk += 16)
            k16_fragB(acc, cu, cu + A_SZ, bfh, bfl, c * 4 + (kk >> 4), nqb, kk, m0, lane);
    }

    const int l4 = lane >> 2, l2 = (lane & 3) << 1;
    const int n0 = nqb * 16;
    if (p == 2) {
        float* dst = g_vf + ((size_t)bh * SS + s0) * KH;
#pragma unroll
        for (int mf = 0; mf < 2; mf++)
#pragma unroll
            for (int nq = 0; nq < 2; nq++)
#pragma unroll
                for (int hf = 0; hf < 2; hf++) {
                    float* c = acc[(mf * 2 + nq) * 2 + hf];
                    int R = m0 + mf * 16 + l4, C = n0 + nq * 16 + hf * 8 + l2;
                    *(float2*)(dst + (size_t)R * KH + C)       = make_float2(c[0], c[1]);
                    *(float2*)(dst + (size_t)(R + 8) * KH + C) = make_float2(c[2], c[3]);
                }
    } else {
        const float sc = (p == 0) ? 0.125f : 1.0f;
        __nv_bfloat16* oh = (p == 0) ? g_qh : g_kh2;
        __nv_bfloat16* ol = (p == 0) ? g_ql : g_kl2;
        size_t rowb = (size_t)bh * SS + s0;
#pragma unroll
        for (int mf = 0; mf < 2; mf++)
#pragma unroll
            for (int nq = 0; nq < 2; nq++)
#pragma unroll
                for (int hf = 0; hf < 2; hf++) {
                    float* c = acc[(mf * 2 + nq) * 2 + hf];
                    int R = m0 + mf * 16 + l4, C = n0 + nq * 16 + hf * 8 + l2;
                    __nv_bfloat16 h0, h1; float lo0, lo1;
                    split1(c[0] * sc, h0, lo0); split1(c[1] * sc, h1, lo1);
                    *(uint32_t*)&oh[(rowb + R) * KH + C] = pk2(__bfloat162float(h0), __bfloat162float(h1));
                    *(uint32_t*)&ol[(rowb + R) * KH + C] = pk2(lo0, lo1);
                    split1(c[2] * sc, h0, lo0); split1(c[3] * sc, h1, lo1);
                    *(uint32_t*)&oh[(rowb + R + 8) * KH + C] = pk2(__bfloat162float(h0), __bfloat162float(h1));
                    *(uint32_t*)&ol[(rowb + R + 8) * KH + C] = pk2(lo0, lo1);
                }
    }
}

// ---------------- flash attention (R12 pipeline; ctx emitted as A-fragments) ----------------
__global__ __launch_bounds__(256, 2) void k_attn() {
    extern __shared__ char sm[];
    const uint32_t sb = cvta_smem(sm);
    const uint32_t aQh = sb, aQl = sb + A_SZ;
    const uint32_t kvb = sb + 2 * A_SZ;

    const int t = threadIdx.x, lane = t & 31, w = t >> 5;
    const int m0 = w * 16;
    const int bh = blockIdx.y, q0 = blockIdx.x * 128;
    const int qG = (q0 >> 4) + w;

    const __nv_bfloat16* kh0 = g_kh2 + (size_t)bh * SS * KH;
    const __nv_bfloat16* kl0 = g_kl2 + (size_t)bh * SS * KH;
    const __nv_bfloat16* vh0 = g_vth + (size_t)bh * KH * SS;
    const __nv_bfloat16* vl0 = g_vtl + (size_t)bh * KH * SS;

#define ISSUE_KV(j, st)                                                   \
    { uint32_t kd = kvb + (uint32_t)((st) * KVSTG);                       \
      cp_tileB(kd + 0 * B_SZ, kh0 + (size_t)(j) * 64 * KH, KH, t);        \
      cp_tileB(kd + 1 * B_SZ, kl0 + (size_t)(j) * 64 * KH, KH, t);        \
      cp_tileB(kd + 2 * B_SZ, vh0 + (j) * 64, SS, t);                     \
      cp_tileB(kd + 3 * B_SZ, vl0 + (j) * 64, SS, t); }

    cp_tileA(aQh, g_qh + ((size_t)bh * SS + q0) * KH, KH, t);
    cp_tileA(aQl, g_ql + ((size_t)bh * SS + q0) * KH, KH, t);
    ISSUE_KV(0, 0)
    CPC();

    float accO[8][4] = {};
    float lr0 = 0.f, lr1 = 0.f;

    for (int j = 0; j < 32; j++) {
        CPW0();
        __syncthreads();
        if (j + 1 < 32) { ISSUE_KV(j + 1, (j + 1) & 1) CPC(); }

        uint32_t kd = kvb + (uint32_t)((j & 1) * KVSTG);
        float s[8][4] = {};
#pragma unroll
        for (int kk = 0; kk < 64; kk += 16)
            k16_all<1, 4>(s, aQh, aQl, kd, kd + B_SZ, kk, m0, 0, lane);

        float p1 = 0.f, p2 = 0.f;
        uint32_t pah[4][4], pal[4][4];
#pragma unroll
        for (int nq = 0; nq < 4; nq++) {
            float eh[8], el[8];
#pragma unroll
            for (int hf = 0; hf < 2; hf++) {
                float* c = s[nq * 2 + hf];
                float e0 = __expf(c[0]), e1 = __expf(c[1]);
                float e2 = __expf(c[2]), e3 = __expf(c[3]);
                p1 += e0 + e1; p2 += e2 + e3;
                __nv_bfloat16 hb; float lo;
                split1(e0, hb, lo); eh[hf * 4 + 0] = __bfloat162float(hb); el[hf * 4 + 0] = lo;
                split1(e1, hb, lo); eh[hf * 4 + 1] = __bfloat162float(hb); el[hf * 4 + 1] = lo;
                split1(e2, hb, lo); eh[hf * 4 + 2] = __bfloat162float(hb); el[hf * 4 + 2] = lo;
                split1(e3, hb, lo); eh[hf * 4 + 3] = __bfloat162float(hb); el[hf * 4 + 3] = lo;
            }
            pah[nq][0] = pk2(eh[0], eh[1]); pah[nq][1] = pk2(eh[2], eh[3]);
            pah[nq][2] = pk2(eh[4], eh[5]); pah[nq][3] = pk2(eh[6], eh[7]);
            pal[nq][0] = pk2(el[0], el[1]); pal[nq][1] = pk2(el[2], el[3]);
            pal[nq][2] = pk2(el[4], el[5]); pal[nq][3] = pk2(el[6], el[7]);
        }
        p1 += __shfl_xor_sync(0xFFFFFFFFu, p1, 1);
        p1 += __shfl_xor_sync(0xFFFFFFFFu, p1, 2);
        p2 += __shfl_xor_sync(0xFFFFFFFFu, p2, 1);
        p2 += __shfl_xor_sync(0xFFFFFFFFu, p2, 2);
        lr0 += p1; lr1 += p2;

#pragma unroll
        for (int nq = 0; nq < 4; nq++)
            k16_pv_reg(accO, pah[nq], pal[nq], kd + 2 * B_SZ, kd + 3 * B_SZ, nq * 16, lane);
    }

    // ctx -> A-fragments for k_out (bit-exact mapping, verified R13)
    const float i0 = 1.f / lr0, i1 = 1.f / lr1;
    const int b = bh >> 4, h = bh & 15;
#pragma unroll
    for (int dn = 0; dn < 4; dn++) {
        float* c0 = accO[dn * 2 + 0];
        float* c1 = accO[dn * 2 + 1];
        float v[8] = {c0[0]*i0, c0[1]*i0, c0[2]*i1, c0[3]*i1,
                      c1[0]*i0, c1[1]*i0, c1[2]*i1, c1[3]*i1};
        size_t idx = (((size_t)b * 128 + qG) * 64 + h * 4 + dn) * 32 + lane;
        g_cfh[idx] = make_uint4(pk2(hi_of(v[0]), hi_of(v[1])), pk2(hi_of(v[2]), hi_of(v[3])),
                                pk2(hi_of(v[4]), hi_of(v[5])), pk2(hi_of(v[6]), hi_of(v[7])));
        g_cfl[idx] = make_uint4(pk2(lo_of(v[0]), lo_of(v[1])), pk2(lo_of(v[2]), lo_of(v[3])),
                                pk2(lo_of(v[4]), lo_of(v[5])), pk2(lo_of(v[6]), lo_of(v[7])));
    }
}

// ---------------- output projection: fully fragment-streamed (R13, verified) ----------------
__global__ __launch_bounds__(256) void k_out(float* __restrict__ out) {
    const int t = threadIdx.x, lane = t & 31, w = t >> 5;
    const int m0 = (w & 3) * 32;
    const int b = blockIdx.x >> 4, s0 = (blockIdx.x & 15) * 128, n0g = blockIdx.y * 64;
    const int nqb = (n0g >> 4) + (w >> 2) * 2;

    float acc[8][4] = {};
    for (int kg = 0; kg < 64; kg++) {
        uint4 ah[2], al[2];
#pragma unroll
        for (int mf = 0; mf < 2; mf++) {
            size_t ai = (((size_t)b * 128 + ((s0 + m0 + mf * 16) >> 4)) * 64 + kg) * 32 + lane;
            ah[mf] = g_cfh[ai];
            al[mf] = g_cfl[ai];
        }
#pragma unroll
        for (int nq = 0; nq < 2; nq++) {
            size_t bi = ((size_t)(nqb + nq) * 64 + kg) * 32 + lane;
            uint4 bh4 = g_wofh[bi];
            uint4 bl4 = g_wofl[bi];
#pragma unroll
            for (int mf = 0; mf < 2; mf++) {
                float* c0 = acc[(mf * 2 + nq) * 2 + 0];
                float* c1 = acc[(mf * 2 + nq) * 2 + 1];
                mma_u4A(c0, ah[mf], bh4.x, bh4.y);
                mma_u4A(c1, ah[mf], bh4.z, bh4.w);
                mma_u4A(c0, ah[mf], bl4.x, bl4.y);
                mma_u4A(c1, ah[mf], bl4.z, bl4.w);
                mma_u4A(c0, al[mf], bh4.x, bh4.y);
                mma_u4A(c1, al[mf], bh4.z, bh4.w);
            }
        }
    }

    const int l4 = lane >> 2, l2 = (lane & 3) << 1;
    const int n0 = (w >> 2) * 32;
    float* dst = out + (size_t)(b * SS + s0) * DD + n0g;
#pragma unroll
    for (int mf = 0; mf < 2; mf++)
#pragma unroll
        for (int nq = 0; nq < 2; nq++)
#pragma unroll
            for (int hf = 0; hf < 2; hf++) {
                float* c = acc[(mf * 2 + nq) * 2 + hf];
                int R = m0 + mf * 16 + l4, C = n0 + nq * 16 + hf * 8 + l2;
                *(float2*)(dst + (size_t)R * DD + C)       = make_float2(c[0], c[1]);
                *(float2*)(dst + (size_t)(R + 8) * DD + C) = make_float2(c[2], c[3]);
            }
}

// ---------------------------------------------------------------------------
extern "C" void kernel_launch(void* const* d_in, const int* in_sizes, int n_in,
                              void* d_out, int out_size) {
    const float* x  = (const float*)d_in[0];
    const float* Wq = (const float*)d_in[1];
    const float* Wk = (const float*)d_in[2];
    const float* Wv = (const float*)d_in[3];
    const float* Wo = (const float*)d_in[4];
    float* out = (float*)d_out;

    cudaFuncSetAttribute(k_qkv,  cudaFuncAttributeMaxDynamicSharedMemorySize, GEMM_SMEM);
    cudaFuncSetAttribute(k_attn, cudaFuncAttributeMaxDynamicSharedMemorySize, ATTN_SMEM);

    k_xsplit<<<(BB * SS * DD) / 256, 256>>>(x);
    k_wsplit<<<1536, 256>>>(Wq, Wk, Wv);
    k_wosplit<<<512, 256>>>(Wo);
    k_qkv<<<dim3(16, NBH, 3), 256, GEMM_SMEM>>>();
    k_vsplit<<<dim3(64, 2, NBH), dim3(32, 8)>>>();
    k_attn<<<dim3(16, NBH), 256, ATTN_SMEM>>>();
    k_out<<<dim3(32, 16), 256>>>(out);
}